// round 16
// baseline (speedup 1.0000x reference)
#include <cuda_runtime.h>
#include <math.h>

#define T      128
#define F      512
#define H      1024
#define RZ     1536
#define RPB    12            // rows per CTA (contiguous)
#define NC     128           // compute CTAs
#define NPF    20            // L2-prefetch CTAs
#define NTH    288           // 256 consumers + 1 bulk-producer thread
#define D      4
#define LOOKAHEAD 12
#define SA     8             // g_acc column stride (floats): 32B per column
#define CSTR   32
#define SLOT_BYTES (RPB * H * 4)      // 49152, contiguous
#define SLOT_WORDS (RPB * H)
#define STEP_LINES (RZ * H * 4 / 128)

__device__ float    g_acc[T * H * SA];   // running sums, bias-initialized
__device__ unsigned g_cnt[T * CSTR];

__global__ void pg_init(const float* __restrict__ bs) {
    int i = blockIdx.x * blockDim.x + threadIdx.x;   // 0 .. T*H-1
    g_acc[(size_t)i * SA] = bs[i];
    if (i < T) g_cnt[i * CSTR] = 0u;
}

__device__ __forceinline__ unsigned ld_acq(const unsigned* p) {
    unsigned v;
    asm volatile("ld.global.acquire.gpu.u32 %0, [%1];" : "=r"(v) : "l"(p) : "memory");
    return v;
}
__device__ __forceinline__ void red_rel(unsigned* p, unsigned v) {
    asm volatile("red.release.gpu.global.add.u32 [%0], %1;" :: "l"(p), "r"(v) : "memory");
}
__device__ __forceinline__ void red_addf(float* p, float v) {
    asm volatile("red.relaxed.gpu.global.add.f32 [%0], %1;" :: "l"(p), "f"(v) : "memory");
}
__device__ __forceinline__ void prefetch_l2(const void* p) {
    asm volatile("prefetch.global.L2 [%0];" :: "l"(p));
}
__device__ __forceinline__ void bar1() {     // consumers only (256 threads)
    asm volatile("bar.sync 1, 256;" ::: "memory");
}
__device__ __forceinline__ void mbar_init(unsigned a, unsigned cnt) {
    asm volatile("mbarrier.init.shared.b64 [%0], %1;" :: "r"(a), "r"(cnt) : "memory");
}
__device__ __forceinline__ void mbar_expect_tx(unsigned a, unsigned bytes) {
    asm volatile("mbarrier.arrive.expect_tx.shared.b64 _, [%0], %1;"
                 :: "r"(a), "r"(bytes) : "memory");
}
__device__ __forceinline__ void mbar_wait(unsigned a, unsigned parity) {
    unsigned done;
    asm volatile(
        "{\n\t.reg .pred p;\n\t"
        "mbarrier.try_wait.parity.acquire.cta.shared::cta.b64 p, [%1], %2;\n\t"
        "selp.b32 %0, 1, 0, p;\n\t}"
        : "=r"(done) : "r"(a), "r"(parity) : "memory");
    if (!done) {
        asm volatile(
            "{\n\t.reg .pred P1;\n\t"
            "WL_%=:\n\t"
            "mbarrier.try_wait.parity.acquire.cta.shared::cta.b64 P1, [%0], %1, 0x989680;\n\t"
            "@P1 bra.uni WD_%=;\n\t"
            "bra.uni WL_%=;\n\t"
            "WD_%=:\n\t}"
            :: "r"(a), "r"(parity) : "memory");
    }
}
__device__ __forceinline__ void bulk_ld(unsigned dst, const void* src,
                                        unsigned bytes, unsigned mbar) {
    asm volatile(
        "cp.async.bulk.shared::cluster.global.mbarrier::complete_tx::bytes "
        "[%0], [%1], %2, [%3];"
        :: "r"(dst), "l"(src), "r"(bytes), "r"(mbar) : "memory");
}

__global__ void __launch_bounds__(NTH, 1) pg_fused(
    const float* __restrict__ x,    // (1, T, F)
    const float* __restrict__ h0,   // (H,)
    const float* __restrict__ Ws,   // (T, RZ, H)
    const float* __restrict__ bs,   // (T, H) (bias folded into g_acc by init)
    const float* __restrict__ Wo,   // (H, 2)
    const float* __restrict__ bo,   // (2,)
    float* __restrict__ out)        // [actors(2), h_final(H)]
{
    extern __shared__ char sm[];
    const int tid = threadIdx.x;

    // ================= L2-prefetch CTAs =================
    if (blockIdx.x >= NC) {
        const int p  = blockIdx.x - NC;
        const int gt = p * NTH + tid;
        for (int t = 0; t < T; ++t) {
            if (t >= LOOKAHEAD) {
                if (tid == 0) {
                    while (ld_acq(&g_cnt[(t - LOOKAHEAD) * CSTR]) != (unsigned)NC) { }
                }
                __syncthreads();
            }
            const char* base = (const char*)(Ws + (size_t)t * RZ * H);
            for (int line = gt; line < STEP_LINES; line += NPF * NTH)
                prefetch_l2(base + (size_t)line * 128);
        }
        return;
    }

    // ================= compute CTAs =================
    float* s_w   = (float*)sm;                           // D x 48KB contiguous tiles
    float* s_z   = (float*)(sm + D * SLOT_BYTES);        // 12 z-values
    float* s_red = s_z + 16;                             // 16 floats (head)
    unsigned long long* s_mb = (unsigned long long*)(s_red + 16);   // D mbarriers
    volatile int* s_consumed = (volatile int*)(s_mb + D);

    const int cg   = blockIdx.x;
    const int row0 = cg * RPB;
    const bool has_h = (row0 + RPB > F);                 // CTA touches h rows?
    unsigned sbase = (unsigned)__cvta_generic_to_shared(s_w);
    unsigned mbase = (unsigned)__cvta_generic_to_shared(s_mb);

    if (tid == 0) {
        for (int i = 0; i < D; ++i) mbar_init(mbase + i * 8, 1u);
        *s_consumed = 0;
    }
    __syncthreads();

    if (tid >= 256) {
        // ---------------- bulk producer (single thread, zero LSU pressure) -------
        if (tid == 256) {
            const float* gbase = Ws + (size_t)row0 * H;
            for (int t = 0; t < T; ++t) {
                while (*s_consumed < t - (D - 1)) { }
                const int slot = t % D;
                unsigned mb = mbase + slot * 8;
                mbar_expect_tx(mb, (unsigned)SLOT_BYTES);
                bulk_ld(sbase + slot * SLOT_BYTES,
                        (const void*)(gbase + (size_t)t * RZ * H),
                        (unsigned)SLOT_BYTES, mb);
            }
        }
        return;
    }

    // ---------------- consumers ----------------
    const int w = tid >> 5, l = tid & 31;
    const int c0 = tid * 4;                              // this thread's 4 columns

    for (int t = 0; t < T; ++t) {
        const int slot = t % D;

        mbar_wait(mbase + slot * 8, (unsigned)((t / D) & 1));   // tile landed

        // ---- acquire h_{t-1} sums (only CTAs owning h rows) ----
        if (has_h && t > 0 && tid == 0) {
            while (ld_acq(&g_cnt[(t - 1) * CSTR]) != (unsigned)NC) { }
        }
        bar1();

        // ---- stage this CTA's 12 z values (x rows direct; h rows = tanh(acc)) ----
        if (tid < RPB) {
            int row = row0 + tid;
            float v;
            if (row < F)      v = __ldg(&x[t * F + row]);
            else if (t == 0)  v = __ldg(&h0[row - F]);
            else              v = tanhf(g_acc[((size_t)(t - 1) * H + (row - F)) * SA]);
            s_z[tid] = v;
        }
        bar1();

        // ---- 48 FMAs: 12 rows x 4 cols, weights from contiguous smem ----
        const float* wslot = s_w + slot * SLOT_WORDS;
        float a0 = 0.f, a1 = 0.f, a2 = 0.f, a3 = 0.f;
#pragma unroll
        for (int i = 0; i < RPB; ++i) {
            float zv = s_z[i];
            float4 wv = *(const float4*)(wslot + i * H + c0);
            a0 = fmaf(zv, wv.x, a0); a1 = fmaf(zv, wv.y, a1);
            a2 = fmaf(zv, wv.z, a2); a3 = fmaf(zv, wv.w, a3);
        }

        // ---- publish: atomic-add partials into this step's column sums ----
        float* dst = g_acc + ((size_t)t * H + c0) * SA;
        red_addf(dst + 0 * SA, a0);
        red_addf(dst + 1 * SA, a1);
        red_addf(dst + 2 * SA, a2);
        red_addf(dst + 3 * SA, a3);

        bar1();                                          // atomics issued + slot read done

        if (tid == 0) {
            *s_consumed = t + 1;                         // recycle slot for bulk engine
            red_rel(&g_cnt[t * CSTR], 1u);               // release step t
        }
    }

    // ---------------- final: h_out, actors (CTA 0) ----------------
    if (cg == 0) {
        if (tid == 0) {
            while (ld_acq(&g_cnt[(T - 1) * CSTR]) != (unsigned)NC) { }
        }
        bar1();
        float r0 = 0.f, r1 = 0.f;
#pragma unroll
        for (int j = 0; j < 4; ++j) {
            int col = c0 + j;
            float hv = tanhf(g_acc[((size_t)(T - 1) * H + col) * SA]);
            out[2 + col] = hv;
            r0 = fmaf(hv, __ldg(&Wo[2 * col + 0]), r0);
            r1 = fmaf(hv, __ldg(&Wo[2 * col + 1]), r1);
        }
#pragma unroll
        for (int off = 16; off >= 1; off >>= 1) {
            r0 += __shfl_xor_sync(0xffffffffu, r0, off);
            r1 += __shfl_xor_sync(0xffffffffu, r1, off);
        }
        if (l == 0) { s_red[w] = r0; s_red[8 + w] = r1; }
        bar1();
        if (tid == 0) {
            float s0 = 0.f, s1 = 0.f;
#pragma unroll
            for (int ww = 0; ww < 8; ++ww) { s0 += s_red[ww]; s1 += s_red[8 + ww]; }
            out[0] = s0 + __ldg(&bo[0]);
            out[1] = s1 + __ldg(&bo[1]);
        }
    }
}

extern "C" void kernel_launch(void* const* d_in, const int* in_sizes, int n_in,
                              void* d_out, int out_size) {
    const float* x  = (const float*)d_in[0];
    const float* h0 = (const float*)d_in[1];
    const float* Ws = (const float*)d_in[2];
    const float* bs = (const float*)d_in[3];
    const float* Wo = (const float*)d_in[4];
    const float* bo = (const float*)d_in[5];
    float* out = (float*)d_out;

    static bool attr_set = false;
    if (!attr_set) {
        cudaFuncSetAttribute(pg_fused, cudaFuncAttributeMaxDynamicSharedMemorySize,
                             D * SLOT_BYTES + 1024);
        attr_set = true;
    }

    pg_init<<<(T * H) / 256, 256>>>(bs);
    pg_fused<<<NC + NPF, NTH, D * SLOT_BYTES + 1024>>>(x, h0, Ws, bs, Wo, bo, out);
}

// round 17
// speedup vs baseline: 1.5373x; 1.5373x over previous
#include <cuda_runtime.h>
#include <math.h>

#define T      128
#define F      512
#define H      1024
#define RZ     1536
#define CPB    8
#define NC     128           // compute CTAs
#define NPF    20            // L2-prefetch CTAs
#define NTH    384           // 256 consumers + 128 producers
#define D      4
#define LOOKAHEAD 12
#define SLOT_BYTES (RZ * CPB * 4)     // 49152
#define SLOT_WORDS (RZ * CPB)
#define STEP_LINES (RZ * H * 4 / 128)

__device__ float    g_h[T * H];
__device__ unsigned g_cnt[T];

__global__ void pg_init() {
    if (threadIdx.x < T) g_cnt[threadIdx.x] = 0u;
}

__device__ __forceinline__ unsigned ld_acq(const unsigned* p) {
    unsigned v;
    asm volatile("ld.global.acquire.gpu.u32 %0, [%1];" : "=r"(v) : "l"(p) : "memory");
    return v;
}
__device__ __forceinline__ void red_rel(unsigned* p, unsigned v) {
    asm volatile("red.release.gpu.global.add.u32 [%0], %1;" :: "l"(p), "r"(v) : "memory");
}
__device__ __forceinline__ void prefetch_l2(const void* p) {
    asm volatile("prefetch.global.L2 [%0];" :: "l"(p));
}
__device__ __forceinline__ void cp_async16(unsigned saddr, const void* gaddr) {
    asm volatile("cp.async.cg.shared.global [%0], [%1], 16;" :: "r"(saddr), "l"(gaddr));
}
__device__ __forceinline__ void cp_commit() { asm volatile("cp.async.commit_group;"); }
template<int N> __device__ __forceinline__ void cp_waitg() {
    asm volatile("cp.async.wait_group %0;" :: "n"(N));
}
__device__ __forceinline__ void bar1() {     // consumers only (256 threads)
    asm volatile("bar.sync 1, 256;" ::: "memory");
}

__global__ void __launch_bounds__(NTH, 1) pg_fused(
    const float* __restrict__ x,    // (1, T, F)
    const float* __restrict__ h0,   // (H,)
    const float* __restrict__ Ws,   // (T, RZ, H)
    const float* __restrict__ bs,   // (T, H)
    const float* __restrict__ Wo,   // (H, 2)
    const float* __restrict__ bo,   // (2,)
    float* __restrict__ out)        // [actors(2), h_final(H)]
{
    extern __shared__ char sm[];
    const int tid = threadIdx.x;

    // ================= prefetch CTAs: keep DRAM streaming ahead =================
    if (blockIdx.x >= NC) {
        const int p  = blockIdx.x - NC;              // 0..19
        const int gt = p * NTH + tid;                // 0..7679
        for (int t = 0; t < T; ++t) {
            if (t >= LOOKAHEAD) {
                if (tid == 0) {
                    while (ld_acq(&g_cnt[t - LOOKAHEAD]) != (unsigned)NC) { }
                }
                __syncthreads();
            }
            const char* base = (const char*)(Ws + (size_t)t * RZ * H);
            for (int line = gt; line < STEP_LINES; line += NPF * NTH)
                prefetch_l2(base + (size_t)line * 128);
        }
        return;
    }

    // ================= compute CTAs =================
    float* s_w   = (float*)sm;                        // D x 48KB z-tiles
    float* s_red = (float*)(sm + D * SLOT_BYTES);     // 64
    int*   s_full = (int*)(s_red + 64);               // D
    volatile int* s_consumed = (volatile int*)(s_full + D);

    const int cg  = blockIdx.x;
    unsigned sbase = (unsigned)__cvta_generic_to_shared(s_w);

    if (tid == 0) {
        for (int i = 0; i < D; ++i) s_full[i] = 0;
        *s_consumed = 0;
    }
    __syncthreads();

    if (tid >= 256) {
        // ---------------- producers: stream full z-tiles ----------------
        const int pt = tid - 256;                      // 0..127
        const float* gcols = Ws + (size_t)cg * CPB;
        for (int t = 0; t < T; ++t) {
            while (*s_consumed < t - (D - 1)) { }
            unsigned sb = sbase + (unsigned)(t % D) * SLOT_BYTES;
            const float* gb = gcols + (size_t)t * RZ * H;
#pragma unroll
            for (int i = 0; i < 24; ++i) {
                int n   = i * 128 + pt;
                int row = n >> 1;
                int cc  = n & 1;
                unsigned soff = sb + (unsigned)(row * 32 + ((cc ^ ((row >> 2) & 1)) << 4));
                cp_async16(soff, (const void*)(gb + (size_t)row * H + cc * 4));
            }
            cp_commit();
            if (t >= 2) {
                cp_waitg<2>();
                __threadfence_block();
                atomicAdd(&s_full[(t - 2) % D], 1);
            }
        }
        cp_waitg<1>(); __threadfence_block(); atomicAdd(&s_full[(T - 2) % D], 1);
        cp_waitg<0>(); __threadfence_block(); atomicAdd(&s_full[(T - 1) % D], 1);
    } else {
        // ---------------- consumers ----------------
        const int w = tid >> 5, l = tid & 31;
        for (int t = 0; t < T; ++t) {
            const int slot = t % D;
            float bval = 0.f;
            if (tid < 8) bval = __ldg(&bs[t * H + cg * CPB + tid]);

            // ---- tile ready? ----
            if (tid == 0) {
                while (((volatile int*)s_full)[slot] != 128) { }
            }
            bar1();

            const float* wslot = s_w + slot * SLOT_WORDS;
            float acc[8];
#pragma unroll
            for (int j = 0; j < 8; ++j) acc[j] = 0.f;

            // ---- x-part (rows 0..511): independent of h, hides the detect ----
#pragma unroll
            for (int i = 0; i < 2; ++i) {
                int r = w * 64 + i * 32 + l;
                float zv = __ldg(&x[t * F + r]);
                int sw = (r >> 2) & 1;
                float4 c0 = *(const float4*)(wslot + r * 8 + sw * 4);
                float4 c1 = *(const float4*)(wslot + r * 8 + (sw ^ 1) * 4);
                acc[0] = fmaf(zv, c0.x, acc[0]); acc[1] = fmaf(zv, c0.y, acc[1]);
                acc[2] = fmaf(zv, c0.z, acc[2]); acc[3] = fmaf(zv, c0.w, acc[3]);
                acc[4] = fmaf(zv, c1.x, acc[4]); acc[5] = fmaf(zv, c1.y, acc[5]);
                acc[6] = fmaf(zv, c1.z, acc[6]); acc[7] = fmaf(zv, c1.w, acc[7]);
            }

            // ---- acquire h_{t-1} ----
            if (tid == 0 && t > 0) {
                while (ld_acq(&g_cnt[t - 1]) != (unsigned)NC) { }
            }
            bar1();

            const float* hp = (t == 0) ? h0 : (g_h + (size_t)(t - 1) * H);
            float zv2[4];
#pragma unroll
            for (int i = 0; i < 4; ++i)                 // issue all 4 LDGs first
                zv2[i] = hp[w * 128 + i * 32 + l];
#pragma unroll
            for (int i = 0; i < 4; ++i) {
                int r = F + w * 128 + i * 32 + l;
                int sw = (r >> 2) & 1;
                float4 c0 = *(const float4*)(wslot + r * 8 + sw * 4);
                float4 c1 = *(const float4*)(wslot + r * 8 + (sw ^ 1) * 4);
                float zv = zv2[i];
                acc[0] = fmaf(zv, c0.x, acc[0]); acc[1] = fmaf(zv, c0.y, acc[1]);
                acc[2] = fmaf(zv, c0.z, acc[2]); acc[3] = fmaf(zv, c0.w, acc[3]);
                acc[4] = fmaf(zv, c1.x, acc[4]); acc[5] = fmaf(zv, c1.y, acc[5]);
                acc[6] = fmaf(zv, c1.z, acc[6]); acc[7] = fmaf(zv, c1.w, acc[7]);
            }

            // ---- reduce over 32 lanes per warp ----
#pragma unroll
            for (int off = 16; off >= 1; off >>= 1)
#pragma unroll
                for (int j = 0; j < 8; ++j)
                    acc[j] += __shfl_xor_sync(0xffffffffu, acc[j], off);
            if (l == 0) {
#pragma unroll
                for (int j = 0; j < 8; ++j) s_red[w * 8 + j] = acc[j];
            }
            bar1();                                   // slot fully consumed here

            if (tid == 0) {                           // recycle the slot
                s_full[slot] = 0;
                __threadfence_block();
                *s_consumed = t + 1;
            }
            // warp 0 finishes the step: combine, tanh, store, release
            if (tid < 8) {
                float s = bval;
#pragma unroll
                for (int ww = 0; ww < 8; ++ww) s += s_red[ww * 8 + tid];
                float hv = tanhf(s);
                int col = cg * CPB + tid;
                g_h[(size_t)t * H + col] = hv;
                if (t == T - 1) out[2 + col] = hv;
            }
            __syncwarp(0xffffffffu);                  // order stores before release
            if (tid == 0) red_rel(&g_cnt[t], 1u);     // ONE atomic per CTA
        }

        // ---------------- actor head (CTA 0) ----------------
        if (cg == 0) {
            if (tid == 0) while (ld_acq(&g_cnt[T - 1]) != (unsigned)NC) { }
            bar1();
            const float* hf = g_h + (size_t)(T - 1) * H;
            float r0 = 0.f, r1 = 0.f;
            for (int i = tid; i < H; i += 256) {
                float hv = hf[i];
                r0 = fmaf(hv, Wo[2 * i + 0], r0);
                r1 = fmaf(hv, Wo[2 * i + 1], r1);
            }
#pragma unroll
            for (int off = 16; off >= 1; off >>= 1) {
                r0 += __shfl_xor_sync(0xffffffffu, r0, off);
                r1 += __shfl_xor_sync(0xffffffffu, r1, off);
            }
            if (l == 0) { s_red[w] = r0; s_red[8 + w] = r1; }
            bar1();
            if (tid == 0) {
                float s0 = 0.f, s1 = 0.f;
#pragma unroll
                for (int ww = 0; ww < 8; ++ww) { s0 += s_red[ww]; s1 += s_red[8 + ww]; }
                out[0] = s0 + bo[0];
                out[1] = s1 + bo[1];
            }
        }
    }
}

extern "C" void kernel_launch(void* const* d_in, const int* in_sizes, int n_in,
                              void* d_out, int out_size) {
    const float* x  = (const float*)d_in[0];
    const float* h0 = (const float*)d_in[1];
    const float* Ws = (const float*)d_in[2];
    const float* bs = (const float*)d_in[3];
    const float* Wo = (const float*)d_in[4];
    const float* bo = (const float*)d_in[5];
    float* out = (float*)d_out;

    static bool attr_set = false;
    if (!attr_set) {
        cudaFuncSetAttribute(pg_fused, cudaFuncAttributeMaxDynamicSharedMemorySize,
                             D * SLOT_BYTES + 1024);
        attr_set = true;
    }

    pg_init<<<1, 128>>>();
    pg_fused<<<NC + NPF, NTH, D * SLOT_BYTES + 1024>>>(x, h0, Ws, bs, Wo, bo, out);
}